// round 5
// baseline (speedup 1.0000x reference)
#include <cuda_runtime.h>

#define DD 4096
#define LL 6
#define BLOCK 1024
// 1024 threads * float4 = 4096 = D; each thread owns 4 columns of every row.

__global__ __launch_bounds__(BLOCK, 1)
void crossnet_dcn_kernel(const float* __restrict__ x0g,
                         const float* __restrict__ wg,
                         const float* __restrict__ bg,
                         float* __restrict__ outg,
                         int B)
{
    __shared__ float s_part[2][32][13];  // double-buffered per-warp partials
    __shared__ float s_c[2][2];          // double-buffered (cA, cB)
    __shared__ float s_e[LL];            // e_l scalars (constant after preamble)

    const int tid  = threadIdx.x;
    const int lane = tid & 31;
    const int wid  = tid >> 5;

    const float4* w4 = reinterpret_cast<const float4*>(wg);
    const float4* b4 = reinterpret_cast<const float4*>(bg);
    const float4* x4 = reinterpret_cast<const float4*>(x0g);
    float4*       o4 = reinterpret_cast<float4*>(outg);

    // ---- w for this thread's 4 columns, all layers (24 regs) ----
    float4 wr[LL];
#pragma unroll
    for (int l = 0; l < LL; l++) wr[l] = w4[l * (DD / 4) + tid];

    // ---- preamble: d_L (vector, regs) and e_l = d_l . w_l (scalars) ----
    float4 dl = make_float4(0.f, 0.f, 0.f, 0.f);
    {
        float ep[LL];
#pragma unroll
        for (int l = 0; l < LL; l++) {
            ep[l] = dl.x * wr[l].x + dl.y * wr[l].y + dl.z * wr[l].z + dl.w * wr[l].w;
            float4 bv = b4[l * (DD / 4) + tid];
            dl.x += bv.x; dl.y += bv.y; dl.z += bv.z; dl.w += bv.w;
        }
#pragma unroll
        for (int o = 16; o > 0; o >>= 1)
#pragma unroll
            for (int l = 0; l < LL; l++) ep[l] += __shfl_xor_sync(0xffffffffu, ep[l], o);
        if (lane == 0)
#pragma unroll
            for (int l = 0; l < LL; l++) s_part[0][wid][l] = ep[l];
    }
    __syncthreads();
    if (wid == 0) {
#pragma unroll
        for (int l = 0; l < LL; l++) {
            float t = s_part[0][lane][l];
#pragma unroll
            for (int o = 16; o > 0; o >>= 1) t += __shfl_xor_sync(0xffffffffu, t, o);
            if (lane == 0) s_e[l] = t;
        }
    }
    __syncthreads();

    // ---- main loop: 2 rows per iteration, ONE barrier per iteration.
    // Stage-2 (warp 0) for pair i overlaps epilogue/stores/prefetch of pair i-1.
    const int npairs = B >> 1;
    const int stride = gridDim.x;

    int pair = blockIdx.x;
    float4 pA = make_float4(0.f, 0.f, 0.f, 0.f);
    float4 pB = pA;
    if (pair < npairs) {
        pA = __ldcs(&x4[(size_t)(2 * pair)     * (DD / 4) + tid]);
        pB = __ldcs(&x4[(size_t)(2 * pair + 1) * (DD / 4) + tid]);
    }

    float4 x0A_prev = pA, x0B_prev = pB;   // init values unused until have_prev
    int    prev_pair = 0;
    bool   have_prev = false;
    int    buf = 0;

    for (; pair < npairs; pair += stride) {
        const float4 x0A = pA;
        const float4 x0B = pB;

        // prefetch next pair (consumed next iteration -> full-iter latency window)
        int np = pair + stride;
        if (np < npairs) {
            pA = __ldcs(&x4[(size_t)(2 * np)     * (DD / 4) + tid]);
            pB = __ldcs(&x4[(size_t)(2 * np + 1) * (DD / 4) + tid]);
        }

        // per-thread partial dots: v[l] = rowA layer l, v[6+l] = rowB layer l
        float v[12];
#pragma unroll
        for (int l = 0; l < LL; l++) {
            float a = x0A.x * wr[l].x;
            a = fmaf(x0A.y, wr[l].y, a);
            a = fmaf(x0A.z, wr[l].z, a);
            a = fmaf(x0A.w, wr[l].w, a);
            v[l] = a;
            float c = x0B.x * wr[l].x;
            c = fmaf(x0B.y, wr[l].y, c);
            c = fmaf(x0B.z, wr[l].z, c);
            c = fmaf(x0B.w, wr[l].w, c);
            v[LL + l] = c;
        }

        // transposed multi-value warp reduce: rounds 16,8,4,2 then xor-1.
        // Value i ends on lanes {2i, 2i+1}.
        {
            bool hi = (lane & 16) != 0;
#pragma unroll
            for (int j = 0; j < 8; j++) {
                float vh   = (j + 8 < 12) ? v[j + 8] : 0.f;
                float send = hi ? v[j] : vh;
                float keep = hi ? vh : v[j];
                v[j] = keep + __shfl_xor_sync(0xffffffffu, send, 16);
            }
        }
#pragma unroll
        for (int r = 1; r < 4; r++) {
            const int dist = 16 >> r;
            const int nv   = 8 >> r;
            bool hi = (lane & dist) != 0;
#pragma unroll
            for (int j = 0; j < nv; j++) {
                float send = hi ? v[j] : v[j + nv];
                float keep = hi ? v[j + nv] : v[j];
                v[j] = keep + __shfl_xor_sync(0xffffffffu, send, dist);
            }
        }
        v[0] += __shfl_xor_sync(0xffffffffu, v[0], 1);

        // one predicated STS: even lanes < 24 hold value idx = lane>>1
        if ((lane & 1) == 0 && lane < 24)
            s_part[buf][wid][lane >> 1] = v[0];

        __syncthreads();   // the ONLY barrier per iteration

        // ---- warp 0: stage-2 for pair i (writes s_c[buf]) ----
        if (wid == 0) {
            float r2[12];
#pragma unroll
            for (int j = 0; j < 12; j++) r2[j] = s_part[buf][lane][j];
            {
                bool hi = (lane & 16) != 0;
#pragma unroll
                for (int j = 0; j < 8; j++) {
                    float vh   = (j + 8 < 12) ? r2[j + 8] : 0.f;
                    float send = hi ? r2[j] : vh;
                    float keep = hi ? vh : r2[j];
                    r2[j] = keep + __shfl_xor_sync(0xffffffffu, send, 16);
                }
            }
#pragma unroll
            for (int r = 1; r < 4; r++) {
                const int dist = 16 >> r;
                const int nv   = 8 >> r;
                bool hi = (lane & dist) != 0;
#pragma unroll
                for (int j = 0; j < nv; j++) {
                    float send = hi ? r2[j] : r2[j + nv];
                    float keep = hi ? r2[j + nv] : r2[j];
                    r2[j] = keep + __shfl_xor_sync(0xffffffffu, send, dist);
                }
            }
            r2[0] += __shfl_xor_sync(0xffffffffu, r2[0], 1);
            // value idx at lane 2*idx: uA_l at 2l, uB_l at 12+2l
            float cA = 1.f, cB = 1.f;
#pragma unroll
            for (int l = 0; l < LL; l++) {
                float uA = __shfl_sync(0xffffffffu, r2[0], 2 * l);
                float uB = __shfl_sync(0xffffffffu, r2[0], 12 + 2 * l);
                float e  = s_e[l];
                cA = fmaf(cA, uA, cA + e);   // c = c*(1+u) + e
                cB = fmaf(cB, uB, cB + e);
            }
            if (lane == 0) { s_c[buf][0] = cA; s_c[buf][1] = cB; }
        }

        // ---- all warps: epilogue for pair i-1 (reads s_c[buf^1]) ----
        if (have_prev) {
            const float cA = s_c[buf ^ 1][0];
            const float cB = s_c[buf ^ 1][1];
            float4 rA, rB;
            rA.x = fmaf(x0A_prev.x, cA, dl.x);
            rA.y = fmaf(x0A_prev.y, cA, dl.y);
            rA.z = fmaf(x0A_prev.z, cA, dl.z);
            rA.w = fmaf(x0A_prev.w, cA, dl.w);
            rB.x = fmaf(x0B_prev.x, cB, dl.x);
            rB.y = fmaf(x0B_prev.y, cB, dl.y);
            rB.z = fmaf(x0B_prev.z, cB, dl.z);
            rB.w = fmaf(x0B_prev.w, cB, dl.w);
            __stcs(&o4[(size_t)(2 * prev_pair)     * (DD / 4) + tid], rA);
            __stcs(&o4[(size_t)(2 * prev_pair + 1) * (DD / 4) + tid], rB);
        }

        x0A_prev = x0A;
        x0B_prev = x0B;
        prev_pair = pair;
        have_prev = true;
        buf ^= 1;
    }

    // ---- drain: epilogue for the last processed pair ----
    if (have_prev) {
        __syncthreads();   // make warp0's s_c[buf^1] visible
        const float cA = s_c[buf ^ 1][0];
        const float cB = s_c[buf ^ 1][1];
        float4 rA, rB;
        rA.x = fmaf(x0A_prev.x, cA, dl.x);
        rA.y = fmaf(x0A_prev.y, cA, dl.y);
        rA.z = fmaf(x0A_prev.z, cA, dl.z);
        rA.w = fmaf(x0A_prev.w, cA, dl.w);
        rB.x = fmaf(x0B_prev.x, cB, dl.x);
        rB.y = fmaf(x0B_prev.y, cB, dl.y);
        rB.z = fmaf(x0B_prev.z, cB, dl.z);
        rB.w = fmaf(x0B_prev.w, cB, dl.w);
        __stcs(&o4[(size_t)(2 * prev_pair)     * (DD / 4) + tid], rA);
        __stcs(&o4[(size_t)(2 * prev_pair + 1) * (DD / 4) + tid], rB);
    }
}

extern "C" void kernel_launch(void* const* d_in, const int* in_sizes, int n_in,
                              void* d_out, int out_size)
{
    const float* x0 = (const float*)d_in[0];   // inputs [B, D] f32
    const float* w  = (const float*)d_in[1];   // w [L, D, 1]  f32
    const float* b  = (const float*)d_in[2];   // b [L, D]     f32
    float* out      = (float*)d_out;           // [B, D]       f32

    const int B = in_sizes[0] / DD;

    static int sm_count = 0;
    if (sm_count == 0) {
        cudaDeviceGetAttribute(&sm_count, cudaDevAttrMultiProcessorCount, 0);
        if (sm_count <= 0) sm_count = 148;
    }

    crossnet_dcn_kernel<<<sm_count, BLOCK>>>(x0, w, b, out, B);
}

// round 6
// speedup vs baseline: 1.8689x; 1.8689x over previous
#include <cuda_runtime.h>
#include <cstdint>

#define DD 4096
#define LL 6
#define BLOCK 1024
#define NST 3            // cp.async pipeline stages (4 rows each)

__device__ __forceinline__ void cp_async16(float* dst, const float* src) {
    uint32_t d = (uint32_t)__cvta_generic_to_shared(dst);
    asm volatile("cp.async.cg.shared.global [%0], [%1], 16;" :: "r"(d), "l"(src));
}
__device__ __forceinline__ void cp_commit() { asm volatile("cp.async.commit_group;"); }
__device__ __forceinline__ void cp_wait1()  { asm volatile("cp.async.wait_group 1;" ::: "memory"); }

__global__ __launch_bounds__(BLOCK, 1)
void crossnet_dcn_kernel(const float* __restrict__ x0g,
                         const float* __restrict__ wg,
                         const float* __restrict__ bg,
                         float* __restrict__ outg,
                         int B)
{
    extern __shared__ float xs[];        // NST * 4 * DD floats (x0 staging)
    __shared__ float s_part[32][25];     // 24 reduced values per warp, pad 25
    __shared__ float s_c[4];             // c scalar per row
    __shared__ float s_e[LL];            // e_l scalars

    const int tid  = threadIdx.x;
    const int lane = tid & 31;
    const int wid  = tid >> 5;

    const float4* w4 = reinterpret_cast<const float4*>(wg);
    const float4* b4 = reinterpret_cast<const float4*>(bg);
    float4*       o4 = reinterpret_cast<float4*>(outg);

    // ---- w for this thread's 4 columns, all layers (24 regs) ----
    float4 wr[LL];
#pragma unroll
    for (int l = 0; l < LL; l++) wr[l] = w4[l * (DD / 4) + tid];

    // ---- preamble: d_L (vector, regs) and e_l = d_l . w_l -> s_e ----
    float4 dl = make_float4(0.f, 0.f, 0.f, 0.f);
    {
        float ep[LL];
#pragma unroll
        for (int l = 0; l < LL; l++) {
            ep[l] = dl.x * wr[l].x + dl.y * wr[l].y + dl.z * wr[l].z + dl.w * wr[l].w;
            float4 bv = b4[l * (DD / 4) + tid];
            dl.x += bv.x; dl.y += bv.y; dl.z += bv.z; dl.w += bv.w;
        }
#pragma unroll
        for (int o = 16; o > 0; o >>= 1)
#pragma unroll
            for (int l = 0; l < LL; l++) ep[l] += __shfl_xor_sync(0xffffffffu, ep[l], o);
        if (lane == 0)
#pragma unroll
            for (int l = 0; l < LL; l++) s_part[wid][l] = ep[l];
    }
    __syncthreads();
    if (wid == 0) {
#pragma unroll
        for (int l = 0; l < LL; l++) {
            float t = s_part[lane][l];
#pragma unroll
            for (int o = 16; o > 0; o >>= 1) t += __shfl_xor_sync(0xffffffffu, t, o);
            if (lane == 0) s_e[l] = t;
        }
    }
    __syncthreads();

    // ---- main loop: 4 rows ("quad") per iteration ----
    const int nquads = B >> 2;
    const int stride = gridDim.x;
    const int bid    = blockIdx.x;
    const int niters = (nquads > bid) ? (nquads - bid + stride - 1) / stride : 0;

    // issue stage for absolute iter 'ia' into slot 'slot' (4 rows, 16B/thread/row)
    auto issue_stage = [&](int ia, int slot) {
        int q = bid + ia * stride;
        if (q < nquads) {
            const float* src = x0g + (size_t)(4 * q) * DD + tid * 4;
            float*       dst = xs + (slot * 4) * DD + tid * 4;
#pragma unroll
            for (int r = 0; r < 4; r++)
                cp_async16(dst + r * DD, src + (size_t)r * DD);
        }
        cp_commit();   // commit even if empty: keeps wait_group accounting uniform
    };

    issue_stage(0, 0);
    issue_stage(1, 1);

    for (int it = 0; it < niters; it++) {
        cp_wait1();                       // slot it%3 ready (own-thread visibility)
        const int  slot = it % NST;
        float* xb = xs + (slot * 4) * DD; // row r at xb + r*DD + tid*4
        const int  q  = bid + it * stride;

        // ---- stage-1: two halves, each = 2 rows x 6 layers = 12 partial dots ----
#pragma unroll
        for (int h = 0; h < 2; h++) {
            const float4 xA = *reinterpret_cast<const float4*>(xb + (2 * h)     * DD + tid * 4);
            const float4 xB = *reinterpret_cast<const float4*>(xb + (2 * h + 1) * DD + tid * 4);
            float v[12];
#pragma unroll
            for (int l = 0; l < LL; l++) {
                float a = xA.x * wr[l].x;
                a = fmaf(xA.y, wr[l].y, a);
                a = fmaf(xA.z, wr[l].z, a);
                a = fmaf(xA.w, wr[l].w, a);
                v[l] = a;
                float c = xB.x * wr[l].x;
                c = fmaf(xB.y, wr[l].y, c);
                c = fmaf(xB.z, wr[l].z, c);
                c = fmaf(xB.w, wr[l].w, c);
                v[LL + l] = c;
            }
            // 16-slot transposed warp reduce (proven): value i -> lanes {2i,2i+1}
            {
                bool hi = (lane & 16) != 0;
#pragma unroll
                for (int j = 0; j < 8; j++) {
                    float vh   = (j + 8 < 12) ? v[j + 8] : 0.f;
                    float send = hi ? v[j] : vh;
                    float keep = hi ? vh : v[j];
                    v[j] = keep + __shfl_xor_sync(0xffffffffu, send, 16);
                }
            }
#pragma unroll
            for (int r = 1; r < 4; r++) {
                const int dist = 16 >> r;
                const int nv   = 8 >> r;
                bool hi = (lane & dist) != 0;
#pragma unroll
                for (int j = 0; j < nv; j++) {
                    float send = hi ? v[j] : v[j + nv];
                    float keep = hi ? v[j + nv] : v[j];
                    v[j] = keep + __shfl_xor_sync(0xffffffffu, send, dist);
                }
            }
            v[0] += __shfl_xor_sync(0xffffffffu, v[0], 1);
            // column 12h+i: i<6 -> row 2h layer i ; i>=6 -> row 2h+1 layer i-6
            if ((lane & 1) == 0 && lane < 24)
                s_part[wid][12 * h + (lane >> 1)] = v[0];
        }

        __syncthreads();   // barrier A

        // refill pipeline: slot (it+2)%3 was last read before barrier A -> safe
        issue_stage(it + 2, (it + 2) % NST);

        // ---- stage-2: warp r reduces row r's 6 values over 32 warps + recurrence ----
        if (wid < 4) {
            float t[6];
#pragma unroll
            for (int l = 0; l < LL; l++) t[l] = s_part[lane][6 * wid + l];
            // 8-slot transposed reduce: value l ends replicated on lanes {4l..4l+3}
            {
                bool hi = (lane & 16) != 0;
#pragma unroll
                for (int j = 0; j < 4; j++) {
                    float th   = (j + 4 < 6) ? t[j + 4] : 0.f;
                    float send = hi ? t[j] : th;
                    float keep = hi ? th : t[j];
                    t[j] = keep + __shfl_xor_sync(0xffffffffu, send, 16);
                }
            }
            {
                bool hi = (lane & 8) != 0;
#pragma unroll
                for (int j = 0; j < 2; j++) {
                    float send = hi ? t[j] : t[j + 2];
                    float keep = hi ? t[j + 2] : t[j];
                    t[j] = keep + __shfl_xor_sync(0xffffffffu, send, 8);
                }
            }
            {
                bool hi = (lane & 4) != 0;
                float send = hi ? t[0] : t[1];
                float keep = hi ? t[1] : t[0];
                t[0] = keep + __shfl_xor_sync(0xffffffffu, send, 4);
            }
            t[0] += __shfl_xor_sync(0xffffffffu, t[0], 2);
            t[0] += __shfl_xor_sync(0xffffffffu, t[0], 1);

            float c = 1.f;
#pragma unroll
            for (int l = 0; l < LL; l++) {
                float u = __shfl_sync(0xffffffffu, t[0], 4 * l);
                c = fmaf(c, u, c + s_e[l]);   // c = c*(1+u) + e
            }
            if (lane == 0) s_c[wid] = c;
        }

        __syncthreads();   // barrier B

        // ---- epilogue: out[row] = x0 * c_row + d_L ----
        const float c0 = s_c[0], c1 = s_c[1], c2 = s_c[2], c3 = s_c[3];
#pragma unroll
        for (int r = 0; r < 4; r++) {
            const float4 x = *reinterpret_cast<const float4*>(xb + r * DD + tid * 4);
            const float  c = (r == 0) ? c0 : (r == 1) ? c1 : (r == 2) ? c2 : c3;
            float4 o;
            o.x = fmaf(x.x, c, dl.x);
            o.y = fmaf(x.y, c, dl.y);
            o.z = fmaf(x.z, c, dl.z);
            o.w = fmaf(x.w, c, dl.w);
            __stcs(&o4[(size_t)(4 * q + r) * (DD / 4) + tid], o);
        }
    }
}

extern "C" void kernel_launch(void* const* d_in, const int* in_sizes, int n_in,
                              void* d_out, int out_size)
{
    const float* x0 = (const float*)d_in[0];   // inputs [B, D] f32
    const float* w  = (const float*)d_in[1];   // w [L, D, 1]  f32
    const float* b  = (const float*)d_in[2];   // b [L, D]     f32
    float* out      = (float*)d_out;           // [B, D]       f32

    const int B = in_sizes[0] / DD;
    const int smem_bytes = NST * 4 * DD * (int)sizeof(float);   // 196608

    static int sm_count = 0;
    if (sm_count == 0) {
        cudaDeviceGetAttribute(&sm_count, cudaDevAttrMultiProcessorCount, 0);
        if (sm_count <= 0) sm_count = 148;
        cudaFuncSetAttribute(crossnet_dcn_kernel,
                             cudaFuncAttributeMaxDynamicSharedMemorySize,
                             smem_bytes);
    }

    crossnet_dcn_kernel<<<sm_count, BLOCK, smem_bytes>>>(x0, w, b, out, B);
}